// round 15
// baseline (speedup 1.0000x reference)
#include <cuda_runtime.h>
#include <cuda_bf16.h>
#include <cuda_fp16.h>
#include <math.h>
#include <stdint.h>

// ---------------- problem constants ----------------
#define BATCH 128
#define C1 256
#define C2 256
#define NMAP 32
#define NPRIM 144
#define NCAP (NMAP*NPRIM)   // 4608
#define NCLS 10
#define OD 16
#define ID 8

#define OUT_OHE_OFF 0
#define OUT_REC_OFF (BATCH*NCLS)
#define OUT_LEN_OFF (BATCH*NCLS + BATCH*784)

// conv2 GEMM geometry (K reordered: k' = (ky*9+kx)*256 + ic)
#define KTOT 20736
#define KC   64
#define NBLK 324
#define MT64 288            // 18432/64 M-tiles

// ---------------- device scratch ----------------
// X packed: [b][px][seg0..3][hi 64 bf16 | lo 64 bf16]  (256B per (px,seg))
__device__ __nv_bfloat16 g_x[(size_t)BATCH*400*4*128];
// W pre-swizzled: [kb][mhalf(2)][plane(2)][krow(64)][256B]
__device__ __nv_bfloat16 g_wsw[(size_t)NBLK*65536/2];
__device__ float g_u[(size_t)BATCH*NCAP*ID];
// u_hat fp16, layout [b][cp(5)][n(4608)][32]
__device__ __half g_uh16[(size_t)BATCH*5*NCAP*32];
__device__ float g_v[BATCH*NCLS*OD];
__device__ float g_vc[BATCH*NCLS*OD];
__device__ int   g_cls[BATCH];
__device__ float g_h1[BATCH*512];
__device__ float g_h2[BATCH*1024];

// ---------------- small PTX helpers ----------------
__device__ __forceinline__ uint32_t smem_u32(const void* p) {
    uint32_t a;
    asm("{ .reg .u64 t; cvta.to.shared.u64 t, %1; cvt.u32.u64 %0, t; }"
        : "=r"(a) : "l"(p));
    return a;
}
__device__ __forceinline__ void ldsm4(uint32_t* r, uint32_t a) {
    asm volatile("ldmatrix.sync.aligned.m8n8.x4.shared.b16 {%0,%1,%2,%3}, [%4];"
        : "=r"(r[0]), "=r"(r[1]), "=r"(r[2]), "=r"(r[3]) : "r"(a));
}
__device__ __forceinline__ void ldsm4t(uint32_t* r, uint32_t a) {
    asm volatile("ldmatrix.sync.aligned.m8n8.x4.trans.shared.b16 {%0,%1,%2,%3}, [%4];"
        : "=r"(r[0]), "=r"(r[1]), "=r"(r[2]), "=r"(r[3]) : "r"(a));
}
__device__ __forceinline__ void mma_bf16(float* c, const uint32_t* a, const uint32_t* b) {
    asm volatile("mma.sync.aligned.m16n8k16.row.col.f32.bf16.bf16.f32 "
        "{%0,%1,%2,%3}, {%4,%5,%6,%7}, {%8,%9}, {%0,%1,%2,%3};"
        : "+f"(c[0]), "+f"(c[1]), "+f"(c[2]), "+f"(c[3])
        : "r"(a[0]), "r"(a[1]), "r"(a[2]), "r"(a[3]), "r"(b[0]), "r"(b[1]));
}
__device__ __forceinline__ void mbar_init(uint32_t mbar, uint32_t cnt) {
    asm volatile("mbarrier.init.shared.b64 [%0], %1;" :: "r"(mbar), "r"(cnt) : "memory");
}
__device__ __forceinline__ void mbar_expect(uint32_t mbar, uint32_t bytes) {
    asm volatile("mbarrier.arrive.expect_tx.shared.b64 _, [%0], %1;"
                 :: "r"(mbar), "r"(bytes) : "memory");
}
__device__ __forceinline__ void bulkcp(uint32_t dst, const void* src, uint32_t size,
                                       uint32_t mbar) {
    asm volatile(
        "cp.async.bulk.shared::cluster.global.mbarrier::complete_tx::bytes [%0], [%1], %2, [%3];"
        :: "r"(dst), "l"(src), "r"(size), "r"(mbar) : "memory");
}
__device__ __forceinline__ void mbar_wait(uint32_t mbar, uint32_t parity) {
    uint32_t done;
    asm volatile("{\n\t.reg .pred p;\n\t"
        "mbarrier.try_wait.parity.acquire.cta.shared::cta.b64 p, [%1], %2;\n\t"
        "selp.b32 %0, 1, 0, p;\n\t}" : "=r"(done) : "r"(mbar), "r"(parity) : "memory");
    while (!done) {
        asm volatile("{\n\t.reg .pred p;\n\t"
            "mbarrier.try_wait.parity.acquire.cta.shared::cta.b64 p, [%1], %2, 0x989680;\n\t"
            "selp.b32 %0, 1, 0, p;\n\t}" : "=r"(done) : "r"(mbar), "r"(parity) : "memory");
    }
}
__device__ __forceinline__ void fence_async_smem() {
    asm volatile("fence.proxy.async.shared::cta;" ::: "memory");
}

// smem per buffer: X 64 rows (272B stride) then W half-image (32KB, 2 planes x 16KB)
#define OFF_X  0u
#define OFF_W  17408u
#define BUFB   50176u
#define CONV2_SMEM (1024u + 2u*BUFB)   // 101376 -> 2 CTAs/SM

// ---------------- fused conv1 + relu + bf16 split + pack into g_x ----------------
#define CONV1_SMEM (812*4 + 2592*4 + 13200*4)   // 66416
__global__ __launch_bounds__(640) void conv1_kernel(
    const float* __restrict__ img, const float* __restrict__ w,
    const float* __restrict__ bias)
{
    extern __shared__ char cs[];
    float* si = (float*)cs;                       // [28][29]
    float* sw = si + 812;                         // [32][81]
    uint32_t* sout = (uint32_t*)(sw + 2592);      // [400][33]

    int octile = blockIdx.x, b = blockIdx.y;
    int t = threadIdx.x;

    for (int i = t; i < 784; i += 640) {
        int r = i / 28, c = i - r*28;
        si[r*29 + c] = img[b*784 + i];
    }
    for (int i = t; i < 32*81; i += 640)
        sw[i] = w[(octile*32 + i/81)*81 + (i % 81)];
    __syncthreads();

    int ocl = t / 20, oy = t % 20;
    float acc[20];
    {
        float bs = bias[octile*32 + ocl];
        #pragma unroll
        for (int ox = 0; ox < 20; ox++) acc[ox] = bs;
    }
    const float* swr = sw + ocl*81;
    #pragma unroll 1
    for (int ky = 0; ky < 9; ky++) {
        const float* row = si + (oy + ky)*29;
        float rv[28];
        #pragma unroll
        for (int i = 0; i < 28; i++) rv[i] = row[i];
        #pragma unroll
        for (int kx = 0; kx < 9; kx++) {
            float wv = swr[ky*9 + kx];
            #pragma unroll
            for (int ox = 0; ox < 20; ox++)
                acc[ox] = fmaf(wv, rv[ox + kx], acc[ox]);
        }
    }
    #pragma unroll
    for (int ox = 0; ox < 20; ox++) {
        float v = fmaxf(acc[ox], 0.f);
        __nv_bfloat16 h = __float2bfloat16(v);
        __nv_bfloat16 l = __float2bfloat16(v - __bfloat162float(h));
        uint32_t pk = (uint32_t)__bfloat16_as_ushort(h)
                    | ((uint32_t)__bfloat16_as_ushort(l) << 16);
        sout[(oy*20 + ox)*33 + ocl] = pk;
    }
    __syncthreads();

    int seg = octile >> 1;
    int iclb = (octile & 1) * 32;
    for (int i = t; i < 400*32; i += 640) {
        int px = i >> 5, c = i & 31;
        uint32_t pk = sout[px*33 + c];
        size_t base = (((size_t)b*400 + px)*4 + seg) * 128;
        g_x[base + iclb + c]      = __ushort_as_bfloat16((unsigned short)(pk & 0xFFFFu));
        g_x[base + 64 + iclb + c] = __ushort_as_bfloat16((unsigned short)(pk >> 16));
    }
}

// ---------------- W split: mhalf-partitioned swizzled chunk images ----------------
// layout per chunk: [mhalf][plane][krow 64][256B]; local col ocl = d*16 + ml
__global__ __launch_bounds__(256) void wsplit_kernel(const float* __restrict__ w2)
{
    extern __shared__ char img[];      // 65536 bytes
    int kb = blockIdx.x;
    int r   = kb >> 2;
    int ic0 = (kb & 3) * 64;
    int t = threadIdx.x;               // = oc
    int mh = (t >> 4) & 1;
    int ml = t & 15;
    int d  = t >> 5;
    int ocl = d*16 + ml;
    const float* src = w2 + (size_t)t*KTOT + (size_t)ic0*81 + r;
    #pragma unroll 4
    for (int icl = 0; icl < 64; icl++) {
        float v = src[icl*81];
        __nv_bfloat16 h = __float2bfloat16(v);
        __nv_bfloat16 l = __float2bfloat16(v - __bfloat162float(h));
        uint32_t byte = (uint32_t)(mh*32768 + icl*256 + ((ocl*2) ^ ((icl & 7) << 4)));
        *(__nv_bfloat16*)(img + byte)         = h;
        *(__nv_bfloat16*)(img + byte + 16384) = l;
    }
    __syncthreads();
    const uint4* s4 = (const uint4*)img;
    uint4* d4 = (uint4*)((char*)g_wsw + (size_t)kb*65536);
    #pragma unroll
    for (int i = 0; i < 16; i++)
        d4[t + i*256] = s4[t + i*256];
}

// ---------------- conv2 tensor-core kernel: M=64, N=128(m-half), 2 CTAs/SM ----------------
__global__ void __launch_bounds__(256, 2) conv2_tc_kernel(const float* __restrict__ b2)
{
    extern __shared__ char smem[];
    uint32_t sbase = smem_u32(smem);
    int t = threadIdx.x;
    int warp = t >> 5, lane = t & 31;
    int mtile = blockIdx.x;
    int mhalf = blockIdx.y;

    int warp_m = warp >> 2;        // 0..1 (32 pos)
    int warp_n = warp & 3;         // 0..3 (32 ocl)

    // X producer mapping: threads 0..63 stage row t; thread 64 stages W
    int trow = (t < 64) ? t : 0;
    int grow = mtile*64 + trow;
    int bimg = grow / NPRIM;
    int posl = grow - bimg*NPRIM;
    int oy = posl / 12, ox = posl - (posl/12)*12;
    int xb400 = bimg*400;

    uint32_t mbar0 = sbase, mbar1 = sbase + 8;
    if (t == 0) { mbar_init(mbar0, 65); mbar_init(mbar1, 65); fence_async_smem(); }
    __syncthreads();

    float acc[2][4][4];
    #pragma unroll
    for (int mt = 0; mt < 2; mt++)
        #pragma unroll
        for (int nt = 0; nt < 4; nt++)
            #pragma unroll
            for (int e = 0; e < 4; e++) acc[mt][nt][e] = 0.f;

    auto stage = [&](int kn, uint32_t buf, uint32_t mbar) {
        if (t < 64) {
            int r = kn >> 2, seg = kn & 3;
            int ky = r / 9, kx = r - ky*9;
            const char* src = (const char*)g_x
                + ((((size_t)(xb400 + (oy+ky)*20 + ox + kx))*4 + seg) << 8);
            mbar_expect(mbar, 256);
            bulkcp(buf + OFF_X + (uint32_t)t*272u, src, 256, mbar);
        } else if (t == 64) {
            mbar_expect(mbar, 32768);
            bulkcp(buf + OFF_W,
                   (const char*)g_wsw + (size_t)kn*65536 + (size_t)mhalf*32768,
                   32768, mbar);
        }
    };

    uint32_t buf0 = sbase + 1024u, buf1 = sbase + 1024u + BUFB;
    stage(0, buf0, mbar0);

    int ph0 = 0, ph1 = 0;
    for (int kb = 0; kb < NBLK; kb++) {
        int cur = kb & 1;
        uint32_t curbuf = cur ? buf1 : buf0;
        if (kb + 1 < NBLK)
            stage(kb + 1, cur ? buf0 : buf1, cur ? mbar0 : mbar1);

        if (cur) { mbar_wait(mbar1, ph1); }
        else     { mbar_wait(mbar0, ph0); }

        #pragma unroll
        for (int kk = 0; kk < 4; kk++) {
            uint32_t bh[4][2], bl[4][2];
            #pragma unroll
            for (int np = 0; np < 2; np++) {
                int j = lane >> 3, rw = lane & 7;
                int krow = kk*16 + (j & 1)*8 + rw;
                int ncol = warp_n*32 + np*16 + (j >> 1)*8;
                uint32_t byte = (uint32_t)(krow*256 + ((ncol*2) ^ ((krow & 7) << 4)));
                uint32_t r[4];
                ldsm4t(r, curbuf + OFF_W + byte);
                bh[2*np][0] = r[0]; bh[2*np][1] = r[1];
                bh[2*np+1][0] = r[2]; bh[2*np+1][1] = r[3];
                ldsm4t(r, curbuf + OFF_W + 16384u + byte);
                bl[2*np][0] = r[0]; bl[2*np][1] = r[1];
                bl[2*np+1][0] = r[2]; bl[2*np+1][1] = r[3];
            }
            #pragma unroll
            for (int mt = 0; mt < 2; mt++) {
                int rowl = warp_m*32 + mt*16 + (lane & 15);
                uint32_t abase = curbuf + OFF_X + (uint32_t)rowl*272u
                               + (uint32_t)((kk*16 + (lane >> 4)*8)*2);
                uint32_t ah[4], al[4];
                ldsm4(ah, abase);
                ldsm4(al, abase + 128u);
                #pragma unroll
                for (int nt = 0; nt < 4; nt++) {
                    mma_bf16(acc[mt][nt], ah, bh[nt]);
                    mma_bf16(acc[mt][nt], ah, bl[nt]);
                    mma_bf16(acc[mt][nt], al, bh[nt]);
                }
            }
        }
        if (cur) ph1 ^= 1; else ph0 ^= 1;
        __syncthreads();
    }

    // ---- fused epilogue: stage D in smem, squash this m-half, write g_u ----
    float* sD = (float*)(smem + 1024);     // [64 pos][stride 132]
    #pragma unroll
    for (int mt = 0; mt < 2; mt++) {
        int pr = warp_m*32 + mt*16 + (lane >> 2);
        #pragma unroll
        for (int half = 0; half < 2; half++) {
            int p2 = pr + half*8;
            #pragma unroll
            for (int nt = 0; nt < 4; nt++) {
                int ocl = warp_n*32 + nt*8 + (lane & 3)*2;
                int d = ocl >> 4, ml = ocl & 15;
                int ocg = d*32 + mhalf*16 + ml;
                sD[p2*132 + ocl]     = acc[mt][nt][half*2 + 0] + __ldg(&b2[ocg]);
                sD[p2*132 + ocl + 1] = acc[mt][nt][half*2 + 1] + __ldg(&b2[ocg+1]);
            }
        }
    }
    __syncthreads();

    #pragma unroll 1
    for (int iter = 0; iter < 4; iter++) {
        int q = iter*256 + t;
        int pos = q & 63;
        int ml  = q >> 6;          // 0..15
        int gq = mtile*64 + pos;
        int b  = gq / NPRIM;
        int pl = gq - b*NPRIM;
        float x[8]; float s2 = 0.f;
        #pragma unroll
        for (int d = 0; d < 8; d++) {
            x[d] = sD[pos*132 + d*16 + ml];
            s2 = fmaf(x[d], x[d], s2);
        }
        float scale = (s2 / (1.f + s2)) / sqrtf(s2 + 1e-8f);
        int m = mhalf*16 + ml;
        float4* up = (float4*)(g_u + ((size_t)b*NCAP + m*NPRIM + pl)*8);
        up[0] = make_float4(scale*x[0], scale*x[1], scale*x[2], scale*x[3]);
        up[1] = make_float4(scale*x[4], scale*x[5], scale*x[6], scale*x[7]);
    }
}

// ---------------- u_hat materialization (fp16, half2 stores, [b][cp][n][32]) ----------------
__global__ __launch_bounds__(320) void uhat16_kernel(const float* __restrict__ Wd)
{
    int t = threadIdx.x;
    int q = t % 80, nl = t / 80;
    int n = blockIdx.x*4 + nl;
    int co0 = 2*q;
    int c = co0 >> 4, o = co0 & 15;
    int cp = c >> 1, cl = c & 1;
    const float4* wr = (const float4*)(Wd + ((size_t)n*160 + co0)*8);
    float4 wa0 = wr[0], wa1 = wr[1], wb0 = wr[2], wb1 = wr[3];
    __half2* outp = (__half2*)(g_uh16 + (((size_t)cp*NCAP + n)*32 + cl*16 + o));
    const float4* up = (const float4*)(g_u + (size_t)n*8);
    const size_t bstride2 = (size_t)5*NCAP*16;   // per-b stride in half2 units
    #pragma unroll 4
    for (int b = 0; b < BATCH; b++) {
        float4 ua = __ldg(up), ub = __ldg(up + 1);
        float a0 = wa0.x*ua.x;
        a0 = fmaf(wa0.y, ua.y, a0); a0 = fmaf(wa0.z, ua.z, a0); a0 = fmaf(wa0.w, ua.w, a0);
        a0 = fmaf(wa1.x, ub.x, a0); a0 = fmaf(wa1.y, ub.y, a0);
        a0 = fmaf(wa1.z, ub.z, a0); a0 = fmaf(wa1.w, ub.w, a0);
        float a1 = wb0.x*ua.x;
        a1 = fmaf(wb0.y, ua.y, a1); a1 = fmaf(wb0.z, ua.z, a1); a1 = fmaf(wb0.w, ua.w, a1);
        a1 = fmaf(wb1.x, ub.x, a1); a1 = fmaf(wb1.y, ub.y, a1);
        a1 = fmaf(wb1.z, ub.z, a1); a1 = fmaf(wb1.w, ub.w, a1);
        outp[(size_t)b*bstride2] = __floats2half2_rn(a0, a1);
        up += NCAP*8/4;
    }
}

// ---------------- routing from materialized fp16 u_hat ----------------
__device__ __forceinline__ void unpack8(const uint4& q, float* f) {
    const __half2* h = (const __half2*)&q;
    #pragma unroll
    for (int j = 0; j < 4; j++) {
        float2 v = __half22float2(h[j]);
        f[2*j] = v.x; f[2*j+1] = v.y;
    }
}

__global__ __launch_bounds__(512) void route16_kernel(int first, int last)
{
    int cp = blockIdx.x;
    int b  = blockIdx.y;
    int t  = threadIdx.x;
    __shared__ float sVc[32];
    __shared__ float sred[16][34];
    __shared__ float sfin[34];

    if (t < 32) sVc[t] = first ? 0.f : g_vc[(b*NCLS + 2*cp + (t >> 4))*OD + (t & 15)];
    __syncthreads();
    float Vc0[16], Vc1[16];
    #pragma unroll
    for (int o = 0; o < 16; o++) { Vc0[o] = sVc[o]; Vc1[o] = sVc[16+o]; }

    float se0 = 0.f, se1 = 0.f;
    float sv0[16], sv1[16];
    #pragma unroll
    for (int o = 0; o < 16; o++) { sv0[o] = 0.f; sv1[o] = 0.f; }

    const __half* ubase = g_uh16 + ((size_t)b*5 + cp)*NCAP*32;

    #pragma unroll 1
    for (int j = 0; j < 9; j++) {
        int n = t + j*512;
        const uint4* up = (const uint4*)(ubase + (size_t)n*32);
        uint4 q0 = up[0], q1 = up[1], q2 = up[2], q3 = up[3];
        float uh0[16], uh1[16];
        unpack8(q0, uh0); unpack8(q1, uh0+8);
        unpack8(q2, uh1); unpack8(q3, uh1+8);
        float b0 = 0.f, b1 = 0.f;
        #pragma unroll
        for (int o = 0; o < 16; o++) {
            b0 = fmaf(uh0[o], Vc0[o], b0);
            b1 = fmaf(uh1[o], Vc1[o], b1);
        }
        float e0 = __expf(b0), e1 = __expf(b1);
        se0 += e0; se1 += e1;
        #pragma unroll
        for (int o = 0; o < 16; o++) {
            sv0[o] = fmaf(e0, uh0[o], sv0[o]);
            sv1[o] = fmaf(e1, uh1[o], sv1[o]);
        }
    }

    #pragma unroll
    for (int off = 16; off > 0; off >>= 1) {
        se0 += __shfl_down_sync(0xffffffffu, se0, off);
        se1 += __shfl_down_sync(0xffffffffu, se1, off);
        #pragma unroll
        for (int o = 0; o < 16; o++) {
            sv0[o] += __shfl_down_sync(0xffffffffu, sv0[o], off);
            sv1[o] += __shfl_down_sync(0xffffffffu, sv1[o], off);
        }
    }
    int wid = t >> 5, lane = t & 31;
    if (lane == 0) {
        sred[wid][0] = se0;
        sred[wid][17] = se1;
        #pragma unroll
        for (int o = 0; o < 16; o++) {
            sred[wid][1+o] = sv0[o];
            sred[wid][18+o] = sv1[o];
        }
    }
    __syncthreads();

    if (t < 34) {
        float tot = 0.f;
        #pragma unroll
        for (int w = 0; w < 16; w++) tot += sred[w][t];
        sfin[t] = tot;
    }
    __syncthreads();

    if (t < 32) {
        int c = t >> 4, o = t & 15;
        float se = sfin[c*17];
        float s = sfin[c*17 + 1 + o] / se;
        float s2 = s*s;
        #pragma unroll
        for (int off = 8; off > 0; off >>= 1)
            s2 += __shfl_xor_sync(0xffffffffu, s2, off, 16);
        float scale = (s2 / (1.f + s2)) / sqrtf(s2 + 1e-8f);
        float vv = scale * s;
        int cls = 2*cp + c;
        g_v[(b*NCLS + cls)*OD + o] = vv;
        if (!last) {
            if (first) g_vc[(b*NCLS + cls)*OD + o] = vv;
            else       g_vc[(b*NCLS + cls)*OD + o] += vv;
        }
    }
}

// ---------------- head ----------------
__global__ void head_kernel(float* __restrict__ out)
{
    int b = blockIdx.x;
    int t = threadIdx.x;
    __shared__ float len[NCLS];
    if (t < NCLS) {
        float s = 0.f;
        #pragma unroll
        for (int o = 0; o < OD; o++) {
            float x = g_v[(b*NCLS + t)*OD + o];
            s = fmaf(x, x, s);
        }
        len[t] = sqrtf(s);
    }
    __syncthreads();
    if (t == 0) {
        int best = 0; float bv = len[0];
        #pragma unroll
        for (int c = 1; c < NCLS; c++)
            if (len[c] > bv) { bv = len[c]; best = c; }
        g_cls[b] = best;
    }
    __syncthreads();
    int best = g_cls[b];
    if (t < NCLS) {
        out[OUT_OHE_OFF + b*NCLS + t] = (t == best) ? 1.0f : 0.0f;
        out[OUT_LEN_OFF + b*NCLS + t] = len[t];
    }
}

// ---------------- decoder ----------------
__global__ void dec1_kernel(const float* __restrict__ w1, const float* __restrict__ b1)
{
    int idx = blockIdx.x*256 + threadIdx.x;
    if (idx >= BATCH*512) return;
    int j = idx % 512, b = idx / 512;
    int cls = g_cls[b];
    const float* v = &g_v[(b*NCLS + cls)*OD];
    float a = b1[j];
    #pragma unroll
    for (int d = 0; d < OD; d++)
        a = fmaf(v[d], w1[(size_t)(cls*OD + d)*512 + j], a);
    g_h1[idx] = fmaxf(a, 0.f);
}

__global__ void dec2_kernel(const float* __restrict__ w2, const float* __restrict__ b2)
{
    int idx = blockIdx.x*256 + threadIdx.x;
    if (idx >= BATCH*1024) return;
    int j = idx % 1024, b = idx / 1024;
    const float* h = &g_h1[b*512];
    float a = b2[j];
    #pragma unroll 4
    for (int k = 0; k < 512; k++)
        a = fmaf(h[k], w2[(size_t)k*1024 + j], a);
    g_h2[idx] = fmaxf(a, 0.f);
}

__global__ void dec3_kernel(const float* __restrict__ w3, const float* __restrict__ b3,
                            float* __restrict__ out)
{
    int idx = blockIdx.x*256 + threadIdx.x;
    if (idx >= BATCH*784) return;
    int p = idx % 784, b = idx / 784;
    const float* h = &g_h2[b*1024];
    float a = b3[p];
    #pragma unroll 4
    for (int k = 0; k < 1024; k++)
        a = fmaf(h[k], w3[(size_t)k*784 + p], a);
    out[OUT_REC_OFF + idx] = 1.f / (1.f + expf(-a));
}

// ---------------- launch ----------------
extern "C" void kernel_launch(void* const* d_in, const int* in_sizes, int n_in,
                              void* d_out, int out_size)
{
    const float* imgs    = (const float*)d_in[0];
    const float* conv1_w = (const float*)d_in[1];
    const float* conv1_b = (const float*)d_in[2];
    const float* conv2_w = (const float*)d_in[3];
    const float* conv2_b = (const float*)d_in[4];
    const float* W_digit = (const float*)d_in[5];
    const float* dec_w1  = (const float*)d_in[6];
    const float* dec_b1  = (const float*)d_in[7];
    const float* dec_w2  = (const float*)d_in[8];
    const float* dec_b2  = (const float*)d_in[9];
    const float* dec_w3  = (const float*)d_in[10];
    const float* dec_b3  = (const float*)d_in[11];
    float* out = (float*)d_out;

    cudaFuncSetAttribute(conv2_tc_kernel,
                         cudaFuncAttributeMaxDynamicSharedMemorySize, CONV2_SMEM);
    cudaFuncSetAttribute(wsplit_kernel,
                         cudaFuncAttributeMaxDynamicSharedMemorySize, 65536);
    cudaFuncSetAttribute(conv1_kernel,
                         cudaFuncAttributeMaxDynamicSharedMemorySize, CONV1_SMEM);

    wsplit_kernel<<<NBLK, 256, 65536>>>(conv2_w);
    conv1_kernel<<<dim3(8, BATCH), 640, CONV1_SMEM>>>(imgs, conv1_w, conv1_b);
    conv2_tc_kernel<<<dim3(MT64, 2), 256, CONV2_SMEM>>>(conv2_b);
    uhat16_kernel<<<NCAP/4, 320>>>(W_digit);
    for (int it = 0; it < 3; it++)
        route16_kernel<<<dim3(5, BATCH), 512>>>(it == 0 ? 1 : 0, it == 2 ? 1 : 0);
    head_kernel<<<BATCH, 32>>>(out);
    dec1_kernel<<<(BATCH*512 + 255)/256, 256>>>(dec_w1, dec_b1);
    dec2_kernel<<<(BATCH*1024 + 255)/256, 256>>>(dec_w2, dec_b2);
    dec3_kernel<<<(BATCH*784 + 255)/256, 256>>>(dec_w3, dec_b3, out);
    (void)in_sizes; (void)n_in; (void)out_size;
}

// round 16
// speedup vs baseline: 1.0334x; 1.0334x over previous
#include <cuda_runtime.h>
#include <cuda_bf16.h>
#include <cuda_fp16.h>
#include <math.h>
#include <stdint.h>

// ---------------- problem constants ----------------
#define BATCH 128
#define C1 256
#define C2 256
#define NMAP 32
#define NPRIM 144
#define NCAP (NMAP*NPRIM)   // 4608
#define NCLS 10
#define OD 16
#define ID 8

#define OUT_OHE_OFF 0
#define OUT_REC_OFF (BATCH*NCLS)
#define OUT_LEN_OFF (BATCH*NCLS + BATCH*784)

// conv2 GEMM geometry (K reordered: k' = (ky*9+kx)*256 + ic)
#define KTOT 20736
#define KC   64
#define NBLK 324
#define MTILES 144

// ---------------- device scratch ----------------
// X packed: [b][px][seg0..3][hi 64 bf16 | lo 64 bf16]  (256B per (px,seg))
__device__ __nv_bfloat16 g_x[(size_t)BATCH*400*4*128];
// W pre-swizzled per 64KB chunk blocks (smem image, both planes)
__device__ __nv_bfloat16 g_wsw[(size_t)NBLK*65536/2];
__device__ float g_u[(size_t)BATCH*NCAP*ID];
// u_hat fp16, layout [b][cp(5)][n(4608)][32]
__device__ __half g_uh16[(size_t)BATCH*5*NCAP*32];
__device__ float g_v[BATCH*NCLS*OD];
__device__ float g_vc[BATCH*NCLS*OD];
__device__ int   g_cls[BATCH];
__device__ float g_h1[BATCH*512];
__device__ float g_h2[BATCH*1024];

// ---------------- small PTX helpers ----------------
__device__ __forceinline__ uint32_t smem_u32(const void* p) {
    uint32_t a;
    asm("{ .reg .u64 t; cvta.to.shared.u64 t, %1; cvt.u32.u64 %0, t; }"
        : "=r"(a) : "l"(p));
    return a;
}
__device__ __forceinline__ void ldsm4(uint32_t* r, uint32_t a) {
    asm volatile("ldmatrix.sync.aligned.m8n8.x4.shared.b16 {%0,%1,%2,%3}, [%4];"
        : "=r"(r[0]), "=r"(r[1]), "=r"(r[2]), "=r"(r[3]) : "r"(a));
}
__device__ __forceinline__ void ldsm4t(uint32_t* r, uint32_t a) {
    asm volatile("ldmatrix.sync.aligned.m8n8.x4.trans.shared.b16 {%0,%1,%2,%3}, [%4];"
        : "=r"(r[0]), "=r"(r[1]), "=r"(r[2]), "=r"(r[3]) : "r"(a));
}
__device__ __forceinline__ void mma_bf16(float* c, const uint32_t* a, const uint32_t* b) {
    asm volatile("mma.sync.aligned.m16n8k16.row.col.f32.bf16.bf16.f32 "
        "{%0,%1,%2,%3}, {%4,%5,%6,%7}, {%8,%9}, {%0,%1,%2,%3};"
        : "+f"(c[0]), "+f"(c[1]), "+f"(c[2]), "+f"(c[3])
        : "r"(a[0]), "r"(a[1]), "r"(a[2]), "r"(a[3]), "r"(b[0]), "r"(b[1]));
}
__device__ __forceinline__ void mbar_init(uint32_t mbar, uint32_t cnt) {
    asm volatile("mbarrier.init.shared.b64 [%0], %1;" :: "r"(mbar), "r"(cnt) : "memory");
}
__device__ __forceinline__ void mbar_expect(uint32_t mbar, uint32_t bytes) {
    asm volatile("mbarrier.arrive.expect_tx.shared.b64 _, [%0], %1;"
                 :: "r"(mbar), "r"(bytes) : "memory");
}
__device__ __forceinline__ void bulkcp(uint32_t dst, const void* src, uint32_t size,
                                       uint32_t mbar) {
    asm volatile(
        "cp.async.bulk.shared::cluster.global.mbarrier::complete_tx::bytes [%0], [%1], %2, [%3];"
        :: "r"(dst), "l"(src), "r"(size), "r"(mbar) : "memory");
}
__device__ __forceinline__ void mbar_wait(uint32_t mbar, uint32_t parity) {
    uint32_t done;
    asm volatile("{\n\t.reg .pred p;\n\t"
        "mbarrier.try_wait.parity.acquire.cta.shared::cta.b64 p, [%1], %2;\n\t"
        "selp.b32 %0, 1, 0, p;\n\t}" : "=r"(done) : "r"(mbar), "r"(parity) : "memory");
    while (!done) {
        asm volatile("{\n\t.reg .pred p;\n\t"
            "mbarrier.try_wait.parity.acquire.cta.shared::cta.b64 p, [%1], %2, 0x989680;\n\t"
            "selp.b32 %0, 1, 0, p;\n\t}" : "=r"(done) : "r"(mbar), "r"(parity) : "memory");
    }
}
__device__ __forceinline__ void fence_async_smem() {
    asm volatile("fence.proxy.async.shared::cta;" ::: "memory");
}

// smem layout per buffer: X rows (272B stride, 128 rows) then W (64KB swizzled image)
#define OFF_X  0u
#define OFF_W  34816u
#define BUFB   100352u
#define CONV2_SMEM (1024u + 2u*BUFB)   // 201728

// ---------------- fused conv1 + relu + bf16 split + pack into g_x ----------------
// grid (8 octiles, BATCH), 640 threads: thread = (ocl 0..31, oy 0..19)
#define CONV1_SMEM (812*4 + 2592*4 + 13200*4)   // 66416
__global__ __launch_bounds__(640) void conv1_kernel(
    const float* __restrict__ img, const float* __restrict__ w,
    const float* __restrict__ bias)
{
    extern __shared__ char cs[];
    float* si = (float*)cs;                       // [28][29]
    float* sw = si + 812;                         // [32][81]
    uint32_t* sout = (uint32_t*)(sw + 2592);      // [400][33]

    int octile = blockIdx.x, b = blockIdx.y;
    int t = threadIdx.x;

    for (int i = t; i < 784; i += 640) {
        int r = i / 28, c = i - r*28;
        si[r*29 + c] = img[b*784 + i];
    }
    for (int i = t; i < 32*81; i += 640)
        sw[i] = w[(octile*32 + i/81)*81 + (i % 81)];
    __syncthreads();

    int ocl = t / 20, oy = t % 20;
    float acc[20];
    {
        float bs = bias[octile*32 + ocl];
        #pragma unroll
        for (int ox = 0; ox < 20; ox++) acc[ox] = bs;
    }
    const float* swr = sw + ocl*81;
    #pragma unroll 1
    for (int ky = 0; ky < 9; ky++) {
        const float* row = si + (oy + ky)*29;
        float rv[28];
        #pragma unroll
        for (int i = 0; i < 28; i++) rv[i] = row[i];
        #pragma unroll
        for (int kx = 0; kx < 9; kx++) {
            float wv = swr[ky*9 + kx];
            #pragma unroll
            for (int ox = 0; ox < 20; ox++)
                acc[ox] = fmaf(wv, rv[ox + kx], acc[ox]);
        }
    }
    #pragma unroll
    for (int ox = 0; ox < 20; ox++) {
        float v = fmaxf(acc[ox], 0.f);
        __nv_bfloat16 h = __float2bfloat16(v);
        __nv_bfloat16 l = __float2bfloat16(v - __bfloat162float(h));
        uint32_t pk = (uint32_t)__bfloat16_as_ushort(h)
                    | ((uint32_t)__bfloat16_as_ushort(l) << 16);
        sout[(oy*20 + ox)*33 + ocl] = pk;
    }
    __syncthreads();

    int seg = octile >> 1;
    int iclb = (octile & 1) * 32;
    for (int i = t; i < 400*32; i += 640) {
        int px = i >> 5, c = i & 31;
        uint32_t pk = sout[px*33 + c];
        size_t base = (((size_t)b*400 + px)*4 + seg) * 128;
        g_x[base + iclb + c]      = __ushort_as_bfloat16((unsigned short)(pk & 0xFFFFu));
        g_x[base + 64 + iclb + c] = __ushort_as_bfloat16((unsigned short)(pk >> 16));
    }
}

// ---------------- W split: block per 64KB chunk, smem-staged coalesced output ----------------
__global__ __launch_bounds__(256) void wsplit_kernel(const float* __restrict__ w2)
{
    extern __shared__ char img[];      // 65536 bytes
    int kb = blockIdx.x;
    int r   = kb >> 2;
    int ic0 = (kb & 3) * 64;
    int t = threadIdx.x;               // = oc
    const float* src = w2 + (size_t)t*KTOT + (size_t)ic0*81 + r;
    #pragma unroll 4
    for (int icl = 0; icl < 64; icl++) {
        float v = src[icl*81];
        __nv_bfloat16 h = __float2bfloat16(v);
        __nv_bfloat16 l = __float2bfloat16(v - __bfloat162float(h));
        uint32_t byte = (uint32_t)(icl*512 + ((t*2) ^ ((icl & 7) << 4)));
        *(__nv_bfloat16*)(img + byte)         = h;
        *(__nv_bfloat16*)(img + byte + 32768) = l;
    }
    __syncthreads();
    const uint4* s4 = (const uint4*)img;
    uint4* d4 = (uint4*)((char*)g_wsw + (size_t)kb*65536);
    #pragma unroll
    for (int i = 0; i < 16; i++)
        d4[t + i*256] = s4[t + i*256];
}

// ---------------- conv2 tensor-core kernel (bulk staging + fused squash epilogue) ----------------
__global__ void __launch_bounds__(512, 1) conv2_tc_kernel(const float* __restrict__ b2)
{
    extern __shared__ char smem[];
    uint32_t sbase = smem_u32(smem);
    int t = threadIdx.x;
    int warp = t >> 5, lane = t & 31;
    int tile = blockIdx.x;

    int warp_m = warp >> 2;
    int warp_n = warp & 3;

    int trow = (t < 128) ? t : 0;
    int grow = tile*128 + trow;
    int bimg = grow / NPRIM;
    int posl = grow - bimg*NPRIM;
    int oy = posl / 12, ox = posl - (posl/12)*12;
    int xb400 = bimg*400;

    uint32_t mbar0 = sbase, mbar1 = sbase + 8;

    if (t == 0) { mbar_init(mbar0, 129); mbar_init(mbar1, 129); fence_async_smem(); }
    __syncthreads();

    float acc[2][8][4];
    #pragma unroll
    for (int mt = 0; mt < 2; mt++)
        #pragma unroll
        for (int nt = 0; nt < 8; nt++)
            #pragma unroll
            for (int e = 0; e < 4; e++) acc[mt][nt][e] = 0.f;

    auto stage = [&](int kn, uint32_t buf, uint32_t mbar) {
        if (t < 128) {
            int r = kn >> 2, seg = kn & 3;
            int ky = r / 9, kx = r - ky*9;
            const char* src = (const char*)g_x
                + ((((size_t)(xb400 + (oy+ky)*20 + ox + kx))*4 + seg) << 8);
            mbar_expect(mbar, 256);
            bulkcp(buf + OFF_X + (uint32_t)t*272u, src, 256, mbar);
        } else if (t == 128) {
            mbar_expect(mbar, 65536);
            bulkcp(buf + OFF_W, (const char*)g_wsw + (size_t)kn*65536, 65536, mbar);
        }
    };

    uint32_t buf0 = sbase + 1024u, buf1 = sbase + 1024u + BUFB;
    stage(0, buf0, mbar0);

    int ph0 = 0, ph1 = 0;
    for (int kb = 0; kb < NBLK; kb++) {
        int cur = kb & 1;
        uint32_t curbuf = cur ? buf1 : buf0;
        if (kb + 1 < NBLK)
            stage(kb + 1, cur ? buf0 : buf1, cur ? mbar0 : mbar1);

        if (cur) { mbar_wait(mbar1, ph1); }
        else     { mbar_wait(mbar0, ph0); }

        #pragma unroll
        for (int kk = 0; kk < 4; kk++) {
            uint32_t bh[8][2], bl[8][2];
            #pragma unroll
            for (int np = 0; np < 4; np++) {
                int j = lane >> 3, rw = lane & 7;
                int krow = kk*16 + (j & 1)*8 + rw;
                int ncol = warp_n*64 + np*16 + (j >> 1)*8;
                uint32_t byte = (uint32_t)(krow*512 + ((ncol*2) ^ ((krow & 7) << 4)));
                uint32_t r[4];
                ldsm4t(r, curbuf + OFF_W + byte);
                bh[2*np][0] = r[0]; bh[2*np][1] = r[1];
                bh[2*np+1][0] = r[2]; bh[2*np+1][1] = r[3];
                ldsm4t(r, curbuf + OFF_W + 32768u + byte);
                bl[2*np][0] = r[0]; bl[2*np][1] = r[1];
                bl[2*np+1][0] = r[2]; bl[2*np+1][1] = r[3];
            }
            #pragma unroll
            for (int mt = 0; mt < 2; mt++) {
                int rowl = warp_m*32 + mt*16 + (lane & 15);
                uint32_t abase = curbuf + OFF_X + (uint32_t)rowl*272u
                               + (uint32_t)((kk*16 + (lane >> 4)*8)*2);
                uint32_t ah[4], al[4];
                ldsm4(ah, abase);
                ldsm4(al, abase + 128u);
                #pragma unroll
                for (int nt = 0; nt < 8; nt++) {
                    mma_bf16(acc[mt][nt], ah, bh[nt]);
                    mma_bf16(acc[mt][nt], ah, bl[nt]);
                    mma_bf16(acc[mt][nt], al, bh[nt]);
                }
            }
        }
        if (cur) ph1 ^= 1; else ph0 ^= 1;
        __syncthreads();
    }

    // ---- fused epilogue: stage D in smem, squash, write g_u directly ----
    float* sD = (float*)(smem + 1024);     // [128 pos][stride 260]
    #pragma unroll
    for (int mt = 0; mt < 2; mt++) {
        int pr = warp_m*32 + mt*16 + (lane >> 2);
        #pragma unroll
        for (int half = 0; half < 2; half++) {
            int p2 = pr + half*8;
            #pragma unroll
            for (int nt = 0; nt < 8; nt++) {
                int oc = warp_n*64 + nt*8 + (lane & 3)*2;
                sD[p2*260 + oc]     = acc[mt][nt][half*2 + 0] + __ldg(&b2[oc]);
                sD[p2*260 + oc + 1] = acc[mt][nt][half*2 + 1] + __ldg(&b2[oc+1]);
            }
        }
    }
    __syncthreads();

    #pragma unroll 1
    for (int iter = 0; iter < 8; iter++) {
        int q = iter*512 + t;
        int pos = q & 127;
        int m   = q >> 7;
        int gq = tile*128 + pos;
        int b  = gq / NPRIM;
        int pl = gq - b*NPRIM;
        float x[8]; float s2 = 0.f;
        #pragma unroll
        for (int d = 0; d < 8; d++) {
            x[d] = sD[pos*260 + m + d*32];
            s2 = fmaf(x[d], x[d], s2);
        }
        float scale = (s2 / (1.f + s2)) / sqrtf(s2 + 1e-8f);
        float4* up = (float4*)(g_u + ((size_t)b*NCAP + m*NPRIM + pl)*8);
        up[0] = make_float4(scale*x[0], scale*x[1], scale*x[2], scale*x[3]);
        up[1] = make_float4(scale*x[4], scale*x[5], scale*x[6], scale*x[7]);
    }
}

// ---------------- u_hat materialization (fp16, half2 stores, [b][cp][n][32]) ----------------
__global__ __launch_bounds__(320) void uhat16_kernel(const float* __restrict__ Wd)
{
    int t = threadIdx.x;
    int q = t % 80, nl = t / 80;
    int n = blockIdx.x*4 + nl;
    int co0 = 2*q;
    int c = co0 >> 4, o = co0 & 15;
    int cp = c >> 1, cl = c & 1;
    const float4* wr = (const float4*)(Wd + ((size_t)n*160 + co0)*8);
    float4 wa0 = wr[0], wa1 = wr[1], wb0 = wr[2], wb1 = wr[3];
    __half2* outp = (__half2*)(g_uh16 + (((size_t)cp*NCAP + n)*32 + cl*16 + o));
    const float4* up = (const float4*)(g_u + (size_t)n*8);
    const size_t bstride2 = (size_t)5*NCAP*16;   // per-b stride in half2 units
    #pragma unroll 4
    for (int b = 0; b < BATCH; b++) {
        float4 ua = __ldg(up), ub = __ldg(up + 1);
        float a0 = wa0.x*ua.x;
        a0 = fmaf(wa0.y, ua.y, a0); a0 = fmaf(wa0.z, ua.z, a0); a0 = fmaf(wa0.w, ua.w, a0);
        a0 = fmaf(wa1.x, ub.x, a0); a0 = fmaf(wa1.y, ub.y, a0);
        a0 = fmaf(wa1.z, ub.z, a0); a0 = fmaf(wa1.w, ub.w, a0);
        float a1 = wb0.x*ua.x;
        a1 = fmaf(wb0.y, ua.y, a1); a1 = fmaf(wb0.z, ua.z, a1); a1 = fmaf(wb0.w, ua.w, a1);
        a1 = fmaf(wb1.x, ub.x, a1); a1 = fmaf(wb1.y, ub.y, a1);
        a1 = fmaf(wb1.z, ub.z, a1); a1 = fmaf(wb1.w, ub.w, a1);
        outp[(size_t)b*bstride2] = __floats2half2_rn(a0, a1);
        up += NCAP*8/4;
    }
}

// ---------------- routing from materialized fp16 u_hat ----------------
__device__ __forceinline__ void unpack8(const uint4& q, float* f) {
    const __half2* h = (const __half2*)&q;
    #pragma unroll
    for (int j = 0; j < 4; j++) {
        float2 v = __half22float2(h[j]);
        f[2*j] = v.x; f[2*j+1] = v.y;
    }
}

__global__ __launch_bounds__(512) void route16_kernel(int first, int last)
{
    int cp = blockIdx.x;
    int b  = blockIdx.y;
    int t  = threadIdx.x;
    __shared__ float sVc[32];
    __shared__ float sred[16][34];
    __shared__ float sfin[34];

    if (t < 32) sVc[t] = first ? 0.f : g_vc[(b*NCLS + 2*cp + (t >> 4))*OD + (t & 15)];
    __syncthreads();
    float Vc0[16], Vc1[16];
    #pragma unroll
    for (int o = 0; o < 16; o++) { Vc0[o] = sVc[o]; Vc1[o] = sVc[16+o]; }

    float se0 = 0.f, se1 = 0.f;
    float sv0[16], sv1[16];
    #pragma unroll
    for (int o = 0; o < 16; o++) { sv0[o] = 0.f; sv1[o] = 0.f; }

    const __half* ubase = g_uh16 + ((size_t)b*5 + cp)*NCAP*32;

    #pragma unroll 1
    for (int j = 0; j < 9; j++) {
        int n = t + j*512;
        const uint4* up = (const uint4*)(ubase + (size_t)n*32);
        uint4 q0 = up[0], q1 = up[1], q2 = up[2], q3 = up[3];
        float uh0[16], uh1[16];
        unpack8(q0, uh0); unpack8(q1, uh0+8);
        unpack8(q2, uh1); unpack8(q3, uh1+8);
        float b0 = 0.f, b1 = 0.f;
        #pragma unroll
        for (int o = 0; o < 16; o++) {
            b0 = fmaf(uh0[o], Vc0[o], b0);
            b1 = fmaf(uh1[o], Vc1[o], b1);
        }
        float e0 = __expf(b0), e1 = __expf(b1);
        se0 += e0; se1 += e1;
        #pragma unroll
        for (int o = 0; o < 16; o++) {
            sv0[o] = fmaf(e0, uh0[o], sv0[o]);
            sv1[o] = fmaf(e1, uh1[o], sv1[o]);
        }
    }

    #pragma unroll
    for (int off = 16; off > 0; off >>= 1) {
        se0 += __shfl_down_sync(0xffffffffu, se0, off);
        se1 += __shfl_down_sync(0xffffffffu, se1, off);
        #pragma unroll
        for (int o = 0; o < 16; o++) {
            sv0[o] += __shfl_down_sync(0xffffffffu, sv0[o], off);
            sv1[o] += __shfl_down_sync(0xffffffffu, sv1[o], off);
        }
    }
    int wid = t >> 5, lane = t & 31;
    if (lane == 0) {
        sred[wid][0] = se0;
        sred[wid][17] = se1;
        #pragma unroll
        for (int o = 0; o < 16; o++) {
            sred[wid][1+o] = sv0[o];
            sred[wid][18+o] = sv1[o];
        }
    }
    __syncthreads();

    if (t < 34) {
        float tot = 0.f;
        #pragma unroll
        for (int w = 0; w < 16; w++) tot += sred[w][t];
        sfin[t] = tot;
    }
    __syncthreads();

    if (t < 32) {
        int c = t >> 4, o = t & 15;
        float se = sfin[c*17];
        float s = sfin[c*17 + 1 + o] / se;
        float s2 = s*s;
        #pragma unroll
        for (int off = 8; off > 0; off >>= 1)
            s2 += __shfl_xor_sync(0xffffffffu, s2, off, 16);
        float scale = (s2 / (1.f + s2)) / sqrtf(s2 + 1e-8f);
        float vv = scale * s;
        int cls = 2*cp + c;
        g_v[(b*NCLS + cls)*OD + o] = vv;
        if (!last) {
            if (first) g_vc[(b*NCLS + cls)*OD + o] = vv;
            else       g_vc[(b*NCLS + cls)*OD + o] += vv;
        }
    }
}

// ---------------- head ----------------
__global__ void head_kernel(float* __restrict__ out)
{
    int b = blockIdx.x;
    int t = threadIdx.x;
    __shared__ float len[NCLS];
    if (t < NCLS) {
        float s = 0.f;
        #pragma unroll
        for (int o = 0; o < OD; o++) {
            float x = g_v[(b*NCLS + t)*OD + o];
            s = fmaf(x, x, s);
        }
        len[t] = sqrtf(s);
    }
    __syncthreads();
    if (t == 0) {
        int best = 0; float bv = len[0];
        #pragma unroll
        for (int c = 1; c < NCLS; c++)
            if (len[c] > bv) { bv = len[c]; best = c; }
        g_cls[b] = best;
    }
    __syncthreads();
    int best = g_cls[b];
    if (t < NCLS) {
        out[OUT_OHE_OFF + b*NCLS + t] = (t == best) ? 1.0f : 0.0f;
        out[OUT_LEN_OFF + b*NCLS + t] = len[t];
    }
}

// ---------------- decoder ----------------
__global__ void dec1_kernel(const float* __restrict__ w1, const float* __restrict__ b1)
{
    int idx = blockIdx.x*256 + threadIdx.x;
    if (idx >= BATCH*512) return;
    int j = idx % 512, b = idx / 512;
    int cls = g_cls[b];
    const float* v = &g_v[(b*NCLS + cls)*OD];
    float a = b1[j];
    #pragma unroll
    for (int d = 0; d < OD; d++)
        a = fmaf(v[d], w1[(size_t)(cls*OD + d)*512 + j], a);
    g_h1[idx] = fmaxf(a, 0.f);
}

__global__ void dec2_kernel(const float* __restrict__ w2, const float* __restrict__ b2)
{
    int idx = blockIdx.x*256 + threadIdx.x;
    if (idx >= BATCH*1024) return;
    int j = idx % 1024, b = idx / 1024;
    const float* h = &g_h1[b*512];
    float a = b2[j];
    #pragma unroll 4
    for (int k = 0; k < 512; k++)
        a = fmaf(h[k], w2[(size_t)k*1024 + j], a);
    g_h2[idx] = fmaxf(a, 0.f);
}

__global__ void dec3_kernel(const float* __restrict__ w3, const float* __restrict__ b3,
                            float* __restrict__ out)
{
    int idx = blockIdx.x*256 + threadIdx.x;
    if (idx >= BATCH*784) return;
    int p = idx % 784, b = idx / 784;
    const float* h = &g_h2[b*1024];
    float a = b3[p];
    #pragma unroll 4
    for (int k = 0; k < 1024; k++)
        a = fmaf(h[k], w3[(size_t)k*784 + p], a);
    out[OUT_REC_OFF + idx] = 1.f / (1.f + expf(-a));
}

// ---------------- launch ----------------
extern "C" void kernel_launch(void* const* d_in, const int* in_sizes, int n_in,
                              void* d_out, int out_size)
{
    const float* imgs    = (const float*)d_in[0];
    const float* conv1_w = (const float*)d_in[1];
    const float* conv1_b = (const float*)d_in[2];
    const float* conv2_w = (const float*)d_in[3];
    const float* conv2_b = (const float*)d_in[4];
    const float* W_digit = (const float*)d_in[5];
    const float* dec_w1  = (const float*)d_in[6];
    const float* dec_b1  = (const float*)d_in[7];
    const float* dec_w2  = (const float*)d_in[8];
    const float* dec_b2  = (const float*)d_in[9];
    const float* dec_w3  = (const float*)d_in[10];
    const float* dec_b3  = (const float*)d_in[11];
    float* out = (float*)d_out;

    cudaFuncSetAttribute(conv2_tc_kernel,
                         cudaFuncAttributeMaxDynamicSharedMemorySize, CONV2_SMEM);
    cudaFuncSetAttribute(wsplit_kernel,
                         cudaFuncAttributeMaxDynamicSharedMemorySize, 65536);
    cudaFuncSetAttribute(conv1_kernel,
                         cudaFuncAttributeMaxDynamicSharedMemorySize, CONV1_SMEM);

    wsplit_kernel<<<NBLK, 256, 65536>>>(conv2_w);
    conv1_kernel<<<dim3(8, BATCH), 640, CONV1_SMEM>>>(imgs, conv1_w, conv1_b);
    conv2_tc_kernel<<<MTILES, 512, CONV2_SMEM>>>(conv2_b);
    uhat16_kernel<<<NCAP/4, 320>>>(W_digit);
    for (int it = 0; it < 3; it++)
        route16_kernel<<<dim3(5, BATCH), 512>>>(it == 0 ? 1 : 0, it == 2 ? 1 : 0);
    head_kernel<<<BATCH, 32>>>(out);
    dec1_kernel<<<(BATCH*512 + 255)/256, 256>>>(dec_w1, dec_b1);
    dec2_kernel<<<(BATCH*1024 + 255)/256, 256>>>(dec_w2, dec_b2);
    dec3_kernel<<<(BATCH*784 + 255)/256, 256>>>(dec_w3, dec_b3, out);
    (void)in_sizes; (void)n_in; (void)out_size;
}